// round 4
// baseline (speedup 1.0000x reference)
#include <cuda_runtime.h>
#include <math.h>

// Problem constants: B=2, L=256, d_e=d_h=512
#define DH   512
#define LSEQ 256
#define MTOT 512   // B*L rows

// ---------------- scratch (no allocations allowed) ----------------
__device__ float g_rep  [MTOT*DH];
__device__ float g_dep2 [MTOT*DH];   // (dep + w1_b + b_logit) * KC
__device__ float g_head2[MTOT*DH];   // (head + w2_b) * KC
__device__ float g_gate1[MTOT*DH];   // rep @ wf1
__device__ float g_attn [MTOT*DH];

typedef unsigned long long ULL;

__device__ __forceinline__ ULL pack2(float x, float y) {
    ULL r; asm("mov.b64 %0, {%1, %2};" : "=l"(r) : "f"(x), "f"(y)); return r;
}
__device__ __forceinline__ void unpack2(ULL v, float &x, float &y) {
    asm("mov.b64 {%0, %1}, %2;" : "=f"(x), "=f"(y) : "l"(v));
}
// packed f32x2 FMA (sm_100+): 2 FMAs per issue slot
__device__ __forceinline__ ULL fma2(ULL a, ULL b, ULL c) {
    ULL d; asm("fma.rn.f32x2 %0, %1, %2, %3;" : "=l"(d) : "l"(a), "l"(b), "l"(c)); return d;
}
__device__ __forceinline__ float ex2f(float x) {
    float r; asm("ex2.approx.f32 %0, %1;" : "=f"(r) : "f"(x)); return r;
}
__device__ __forceinline__ float rcpf(float x) {
    float r; asm("rcp.approx.f32 %0, %1;" : "=f"(r) : "f"(x)); return r;
}

// logits = C*tanh((dep+head+b_logit)/C), C=5.
// t = exp(-2u) = exp2((dep'+head')*KC) with KC = -2*log2e/C
// tanh = 2/(1+t) - 1  (robust for t->0 and t->inf)
// w = exp(C*tanh) = exp2(TWO_C2 * rcp(1+t) - C2)
#define LOG2E  1.4426950408889634f
#define KCNST  (-0.57707801635558536f)   // -2*LOG2E/5
#define C2CNST (7.2134752044448170f)     // 5*LOG2E
#define TWOC2  (14.426950408889634f)

// =====================================================================
// GEMM: C[512, N] = A[512,512] @ B[512,N], BM=64, BN=32, BK=16, 128 thr
// MODE 0: A=x,        B=fc_w,          epi: elu -> g_rep
// MODE 1: A=g_rep,    B in {w1,w2,wf1} per region, epi -> dep2/head2/gate1
// MODE 2: A=g_attn,   B=wf2,           epi: gate fusion -> dout
// =====================================================================
template<int MODE>
__global__ void __launch_bounds__(128) gemm_kernel(
    const float* __restrict__ Ain,
    const float* __restrict__ W0, const float* __restrict__ W1,
    const float* __restrict__ W2,
    const float* __restrict__ bias0, const float* __restrict__ bias1,
    const float* __restrict__ blog,
    float* __restrict__ dout)
{
    __shared__ __align__(16) float As[2][16][64];
    __shared__ __align__(16) float Bs[2][16][32];

    const int tid = threadIdx.x;
    const int m0  = blockIdx.x * 64;
    int nt = blockIdx.y;
    int region = 0;
    const float* B = W0;
    if (MODE == 1) {                 // 48 N-tiles: 16 per weight
        region = nt >> 4; nt &= 15;
        B = (region == 0) ? W0 : (region == 1 ? W1 : W2);
    }
    const int n0 = nt * 32;

    const float* Ap = (MODE == 0) ? Ain : (MODE == 1 ? g_rep : g_attn);

    // A tile loaders: 256 float4 -> 2/thread; (row, c4) unique per thread
    const int a_c4  = tid >> 6;      // 0..1 (+2 for second load)
    const int a_row = tid & 63;
    // B tile loaders: 128 float4 -> 1/thread
    const int b_r  = tid >> 3;       // 0..15
    const int b_c4 = tid & 7;        // 0..7

    const float* Arow = Ap + (m0 + a_row) * DH + a_c4 * 4;
    const float* Brow = B + b_r * DH + n0 + b_c4 * 4;

    const int tm8 = (tid >> 4) * 8;  // 8 M rows / thread
    const int tn2 = (tid & 15) * 2;  // 2 N cols / thread

    float4 ra0, ra1, rb0;
    // prologue: k-tile 0
    ra0 = *(const float4*)(Arow);
    ra1 = *(const float4*)(Arow + 8);
    rb0 = *(const float4*)(Brow);
    {
        const int c0 = a_c4 * 4, c1 = (a_c4 + 2) * 4;
        As[0][c0+0][a_row] = ra0.x; As[0][c0+1][a_row] = ra0.y;
        As[0][c0+2][a_row] = ra0.z; As[0][c0+3][a_row] = ra0.w;
        As[0][c1+0][a_row] = ra1.x; As[0][c1+1][a_row] = ra1.y;
        As[0][c1+2][a_row] = ra1.z; As[0][c1+3][a_row] = ra1.w;
        *(float4*)&Bs[0][b_r][b_c4 * 4] = rb0;
    }
    __syncthreads();

    ULL acc[4][2] = {};  // [M pair][N col] packed f32x2 along M

    int buf = 0;
    #pragma unroll 1
    for (int kt = 0; kt < 32; ++kt) {
        if (kt < 31) {
            const int k0 = (kt + 1) * 16;
            ra0 = *(const float4*)(Arow + k0);
            ra1 = *(const float4*)(Arow + k0 + 8);
            rb0 = *(const float4*)(Brow + (size_t)k0 * DH);
        }
        #pragma unroll
        for (int kk = 0; kk < 16; ++kk) {
            ulonglong2 av0 = *(const ulonglong2*)&As[buf][kk][tm8];
            ulonglong2 av1 = *(const ulonglong2*)&As[buf][kk][tm8 + 4];
            float2 bv = *(const float2*)&Bs[buf][kk][tn2];
            ULL b0 = pack2(bv.x, bv.x);
            ULL b1 = pack2(bv.y, bv.y);
            acc[0][0] = fma2(av0.x, b0, acc[0][0]);
            acc[0][1] = fma2(av0.x, b1, acc[0][1]);
            acc[1][0] = fma2(av0.y, b0, acc[1][0]);
            acc[1][1] = fma2(av0.y, b1, acc[1][1]);
            acc[2][0] = fma2(av1.x, b0, acc[2][0]);
            acc[2][1] = fma2(av1.x, b1, acc[2][1]);
            acc[3][0] = fma2(av1.y, b0, acc[3][0]);
            acc[3][1] = fma2(av1.y, b1, acc[3][1]);
        }
        if (kt < 31) {
            const int nb = buf ^ 1;
            const int c0 = a_c4 * 4, c1 = (a_c4 + 2) * 4;
            As[nb][c0+0][a_row] = ra0.x; As[nb][c0+1][a_row] = ra0.y;
            As[nb][c0+2][a_row] = ra0.z; As[nb][c0+3][a_row] = ra0.w;
            As[nb][c1+0][a_row] = ra1.x; As[nb][c1+1][a_row] = ra1.y;
            As[nb][c1+2][a_row] = ra1.z; As[nb][c1+3][a_row] = ra1.w;
            *(float4*)&Bs[nb][b_r][b_c4 * 4] = rb0;
            __syncthreads();
            buf = nb;
        }
    }

    // ----------------- epilogue -----------------
    #pragma unroll
    for (int mp = 0; mp < 4; ++mp) {
        const int row = m0 + tm8 + mp * 2;
        #pragma unroll
        for (int n = 0; n < 2; ++n) {
            float lo, hi; unpack2(acc[mp][n], lo, hi);
            const int col = n0 + tn2 + n;
            const int i0 = row * DH + col;
            const int i1 = i0 + DH;
            if (MODE == 0) {
                const float b = bias0[col];
                const float v0 = lo + b, v1 = hi + b;
                g_rep[i0] = v0 > 0.f ? v0 : expm1f(v0);
                g_rep[i1] = v1 > 0.f ? v1 : expm1f(v1);
            } else if (MODE == 1) {
                if (region == 0) {
                    const float b = bias0[col] + blog[col];
                    g_dep2[i0] = (lo + b) * KCNST;
                    g_dep2[i1] = (hi + b) * KCNST;
                } else if (region == 1) {
                    const float b = bias1[col];
                    g_head2[i0] = (lo + b) * KCNST;
                    g_head2[i1] = (hi + b) * KCNST;
                } else {
                    g_gate1[i0] = lo;
                    g_gate1[i1] = hi;
                }
            } else {
                const float b = bias0[col];   // bf
                const float z0 = g_gate1[i0] + lo + b;
                const float z1 = g_gate1[i1] + hi + b;
                const float gg0 = 1.f / (1.f + expf(-z0));
                const float gg1 = 1.f / (1.f + expf(-z1));
                const float a0 = g_attn[i0], a1 = g_attn[i1];
                dout[i0] = fmaf(gg0, g_rep[i0] - a0, a0);
                dout[i1] = fmaf(gg1, g_rep[i1] - a1, a1);
            }
        }
    }
}

// =====================================================================
// Fused masked tanh-logit softmax + weighted sum over dependents.
// CTA = (batch, pair p). p<127: rows {p, 254-p} (work p+1 and 255-p sum
// to a constant 256, and the j-ranges nest so loads are shared).
// p=127: row 127 alone.
// p=128: row 255. This row is FULLY masked. In fp32 the reference's
//   logits + (-1e9) rounds to exactly -1e9 for every j (ulp(1e9)=64 >>
//   |C*tanh|<=5), so the reference softmax is exactly UNIFORM 1/256.
//   We must reproduce that: attn_out[255] = mean_j rep[j].
// threads = 512 channels.
// =====================================================================
__device__ __forceinline__ float wfun(float x) {
    const float t = ex2f(x);             // exp(-2u)
    const float r = rcpf(1.f + t);
    return ex2f(fmaf(TWOC2, r, -C2CNST)); // exp(C*tanh(u))
}

__global__ void __launch_bounds__(512) attn_kernel()
{
    const int cta = blockIdx.x;
    const int b = cta / 129;
    const int p = cta - b * 129;
    const int h = threadIdx.x;

    const float* __restrict__ dep = g_dep2  + b * LSEQ * DH;
    const float* __restrict__ hd  = g_head2 + b * LSEQ * DH;
    const float* __restrict__ rp  = g_rep   + b * LSEQ * DH;

    if (p == 128) {
        // Row 255: fully masked -> reference collapses to uniform weights
        // (fp32 absorption of C*tanh into -1e9). attn = mean_j rep[j].
        float s = 0.f;
        #pragma unroll 8
        for (int j = 0; j < LSEQ; ++j)
            s += rp[j * DH + h];
        g_attn[(b * LSEQ + 255) * DH + h] = s * (1.0f / 256.0f);
        return;
    }

    int i1, i2, jstart, jmid;
    if (p < 127)       { i1 = p;   i2 = 254 - p; jstart = p + 1; jmid = 255 - p; }
    else               { i1 = 127; i2 = -1;      jstart = 128;   jmid = 256; }

    const float h1 = hd[i1 * DH + h];
    const float h2 = (i2 >= 0) ? hd[i2 * DH + h] : 0.f;

    float n1 = 0.f, d1 = 0.f, n2 = 0.f, d2 = 0.f;
    int j = jstart;
    #pragma unroll 4
    for (; j < jmid; ++j) {
        const float dj = dep[j * DH + h];
        const float rj = rp [j * DH + h];
        const float w  = wfun(dj + h1);
        n1 = fmaf(w, rj, n1); d1 += w;
    }
    #pragma unroll 4
    for (; j < 256; ++j) {
        const float dj = dep[j * DH + h];
        const float rj = rp [j * DH + h];
        const float wa = wfun(dj + h1);
        n1 = fmaf(wa, rj, n1); d1 += wa;
        const float wb = wfun(dj + h2);
        n2 = fmaf(wb, rj, n2); d2 += wb;
    }
    g_attn[(b * LSEQ + i1) * DH + h] = n1 / d1;
    if (i2 >= 0)
        g_attn[(b * LSEQ + i2) * DH + h] = n2 / d2;
}

// =====================================================================
extern "C" void kernel_launch(void* const* d_in, const int* in_sizes, int n_in,
                              void* d_out, int out_size)
{
    const float* x       = (const float*)d_in[0];
    const float* fc_w    = (const float*)d_in[1];
    const float* fc_b    = (const float*)d_in[2];
    const float* w1_w    = (const float*)d_in[3];
    const float* w1_b    = (const float*)d_in[4];
    const float* w2_w    = (const float*)d_in[5];
    const float* w2_b    = (const float*)d_in[6];
    const float* b_logit = (const float*)d_in[7];
    const float* wf1_w   = (const float*)d_in[8];
    const float* wf2_w   = (const float*)d_in[9];
    const float* bf      = (const float*)d_in[10];
    float* out = (float*)d_out;

    // 1) rep = elu(x @ fc_w + fc_b)
    gemm_kernel<0><<<dim3(8, 16), 128>>>(x, fc_w, nullptr, nullptr,
                                         fc_b, nullptr, nullptr, nullptr);
    // 2) dep2/head2/gate1 = rep @ {w1,w2,wf1} (+biases, pre-scaled for exp2)
    gemm_kernel<1><<<dim3(8, 48), 128>>>(nullptr, w1_w, w2_w, wf1_w,
                                         w1_b, w2_b, b_logit, nullptr);
    // 3) fused masked softmax attention over dependents
    attn_kernel<<<2 * 129, 512>>>();
    // 4) out = sigmoid(gate1 + attn@wf2 + bf) * rep + (1-g) * attn
    gemm_kernel<2><<<dim3(8, 16), 128>>>(nullptr, wf2_w, nullptr, nullptr,
                                         bf, nullptr, nullptr, out);
}

// round 5
// speedup vs baseline: 1.1237x; 1.1237x over previous
#include <cuda_runtime.h>
#include <math.h>

// Problem constants: B=2, L=256, d_e=d_h=512
#define DH   512
#define LSEQ 256
#define MTOT 512   // B*L rows
#define NSPLIT 4   // split-K factor
#define NTOT1 1536 // mode-1 total output columns (3 weights)

// ---------------- scratch (no allocations allowed) ----------------
__device__ float g_rep  [MTOT*DH];
__device__ float g_dep2 [MTOT*DH];   // (dep + w1_b + b_logit) * KC
__device__ float g_head2[MTOT*DH];   // (head + w2_b) * KC
__device__ float g_gate1[MTOT*DH];   // rep @ wf1
__device__ float g_attn [MTOT*DH];
__device__ float g_part [NSPLIT][MTOT*NTOT1];   // split-K partials (12.6 MB)

typedef unsigned long long ULL;

__device__ __forceinline__ ULL pack2(float x, float y) {
    ULL r; asm("mov.b64 %0, {%1, %2};" : "=l"(r) : "f"(x), "f"(y)); return r;
}
__device__ __forceinline__ void unpack2(ULL v, float &x, float &y) {
    asm("mov.b64 {%0, %1}, %2;" : "=f"(x), "=f"(y) : "l"(v));
}
// packed f32x2 FMA (sm_100+): 2 FMAs per issue slot
__device__ __forceinline__ ULL fma2(ULL a, ULL b, ULL c) {
    ULL d; asm("fma.rn.f32x2 %0, %1, %2, %3;" : "=l"(d) : "l"(a), "l"(b), "l"(c)); return d;
}
__device__ __forceinline__ float ex2f(float x) {
    float r; asm("ex2.approx.f32 %0, %1;" : "=f"(r) : "f"(x)); return r;
}
__device__ __forceinline__ float rcpf(float x) {
    float r; asm("rcp.approx.f32 %0, %1;" : "=f"(r) : "f"(x)); return r;
}

// logits = C*tanh((dep+head+b_logit)/C), C=5.
// t = exp(-2u) = exp2((dep'+head')) with dep',head' pre-scaled by KC = -2*log2e/C
// tanh = 2/(1+t) - 1 ; w = exp(C*tanh) = exp2(TWOC2 * rcp(1+t) - C2)
#define KCNST  (-0.57707801635558536f)   // -2*log2e/5
#define C2CNST (7.2134752044448170f)     // 5*log2e
#define TWOC2  (14.426950408889634f)

// =====================================================================
// Split-K GEMM: partial C[64,32] over K range [ks*128,(ks+1)*128)
// -> g_part[ks]. BM=64, BN=32, BK=16, 128 threads.
// MODE 0: A=x,      B=fc_w                (NTOT=512)
// MODE 1: A=g_rep,  B in {w1,w2,wf1}      (NTOT=1536, 16 N-tiles each)
// MODE 2: A=g_attn, B=wf2                 (NTOT=512)
// =====================================================================
template<int MODE>
__global__ void __launch_bounds__(128) gemm_split_kernel(
    const float* __restrict__ Ain,
    const float* __restrict__ W0, const float* __restrict__ W1,
    const float* __restrict__ W2)
{
    constexpr int NTOT = (MODE == 1) ? NTOT1 : DH;

    __shared__ __align__(16) float As[2][16][64];
    __shared__ __align__(16) float Bs[2][16][32];

    const int tid = threadIdx.x;
    const int m0  = blockIdx.x * 64;
    const int nt  = blockIdx.y;
    const int ks  = blockIdx.z;           // split index 0..3
    const int colbase = nt * 32;          // scratch column base

    const float* B = W0;
    int nw0 = colbase;                    // column within the weight matrix
    if (MODE == 1) {
        const int region = nt >> 4;
        B = (region == 0) ? W0 : (region == 1 ? W1 : W2);
        nw0 = (nt & 15) * 32;
    }
    const float* Ap = (MODE == 0) ? Ain : (MODE == 1 ? g_rep : g_attn);

    // A tile loaders: 256 float4 -> 2/thread
    const int a_c4  = tid >> 6;           // 0..1 (+2 for second load)
    const int a_row = tid & 63;
    // B tile loaders: 128 float4 -> 1/thread
    const int b_r  = tid >> 3;            // 0..15
    const int b_c4 = tid & 7;             // 0..7

    const float* Arow = Ap + (m0 + a_row) * DH + ks * 128 + a_c4 * 4;
    const float* Brow = B + (ks * 128 + b_r) * DH + nw0 + b_c4 * 4;

    const int tm8 = (tid >> 4) * 8;       // 8 M rows / thread
    const int tn2 = (tid & 15) * 2;       // 2 N cols / thread

    float4 ra0, ra1, rb0;
    // prologue: k-tile 0
    ra0 = *(const float4*)(Arow);
    ra1 = *(const float4*)(Arow + 8);
    rb0 = *(const float4*)(Brow);
    {
        const int c0 = a_c4 * 4, c1 = (a_c4 + 2) * 4;
        As[0][c0+0][a_row] = ra0.x; As[0][c0+1][a_row] = ra0.y;
        As[0][c0+2][a_row] = ra0.z; As[0][c0+3][a_row] = ra0.w;
        As[0][c1+0][a_row] = ra1.x; As[0][c1+1][a_row] = ra1.y;
        As[0][c1+2][a_row] = ra1.z; As[0][c1+3][a_row] = ra1.w;
        *(float4*)&Bs[0][b_r][b_c4 * 4] = rb0;
    }
    __syncthreads();

    ULL acc[4][2] = {};  // [M pair][N col] packed f32x2 along M

    int buf = 0;
    #pragma unroll 1
    for (int kt = 0; kt < 8; ++kt) {
        if (kt < 7) {
            const int k0 = (kt + 1) * 16;
            ra0 = *(const float4*)(Arow + k0);
            ra1 = *(const float4*)(Arow + k0 + 8);
            rb0 = *(const float4*)(Brow + (size_t)k0 * DH);
        }
        #pragma unroll
        for (int kk = 0; kk < 16; ++kk) {
            ulonglong2 av0 = *(const ulonglong2*)&As[buf][kk][tm8];
            ulonglong2 av1 = *(const ulonglong2*)&As[buf][kk][tm8 + 4];
            float2 bv = *(const float2*)&Bs[buf][kk][tn2];
            ULL b0 = pack2(bv.x, bv.x);
            ULL b1 = pack2(bv.y, bv.y);
            acc[0][0] = fma2(av0.x, b0, acc[0][0]);
            acc[0][1] = fma2(av0.x, b1, acc[0][1]);
            acc[1][0] = fma2(av0.y, b0, acc[1][0]);
            acc[1][1] = fma2(av0.y, b1, acc[1][1]);
            acc[2][0] = fma2(av1.x, b0, acc[2][0]);
            acc[2][1] = fma2(av1.x, b1, acc[2][1]);
            acc[3][0] = fma2(av1.y, b0, acc[3][0]);
            acc[3][1] = fma2(av1.y, b1, acc[3][1]);
        }
        if (kt < 7) {
            const int nb = buf ^ 1;
            const int c0 = a_c4 * 4, c1 = (a_c4 + 2) * 4;
            As[nb][c0+0][a_row] = ra0.x; As[nb][c0+1][a_row] = ra0.y;
            As[nb][c0+2][a_row] = ra0.z; As[nb][c0+3][a_row] = ra0.w;
            As[nb][c1+0][a_row] = ra1.x; As[nb][c1+1][a_row] = ra1.y;
            As[nb][c1+2][a_row] = ra1.z; As[nb][c1+3][a_row] = ra1.w;
            *(float4*)&Bs[nb][b_r][b_c4 * 4] = rb0;
            __syncthreads();
            buf = nb;
        }
    }

    // ----- write partials: 8 x STG.64 per thread -----
    float* dst = &g_part[ks][0];
    #pragma unroll
    for (int mp = 0; mp < 4; ++mp) {
        const int row = m0 + tm8 + mp * 2;
        float lo0, hi0, lo1, hi1;
        unpack2(acc[mp][0], lo0, hi0);
        unpack2(acc[mp][1], lo1, hi1);
        *(float2*)&dst[(size_t)row * NTOT + colbase + tn2]       = make_float2(lo0, lo1);
        *(float2*)&dst[(size_t)(row + 1) * NTOT + colbase + tn2] = make_float2(hi0, hi1);
    }
}

// =====================================================================
// Reduce 4 split-K partials + epilogue.  One float4 per thread.
// MODE 0: g_rep = elu(s + fc_b)
// MODE 1: region 0 -> g_dep2 = (s + w1_b + b_logit)*KC
//         region 1 -> g_head2 = (s + w2_b)*KC
//         region 2 -> g_gate1 = s
// MODE 2: dout = sigmoid(g_gate1 + s + bf) blend of g_rep / g_attn
// =====================================================================
template<int MODE>
__global__ void __launch_bounds__(256) epi_kernel(
    const float* __restrict__ bias0, const float* __restrict__ bias1,
    const float* __restrict__ blog, float* __restrict__ dout)
{
    constexpr int NTOT = (MODE == 1) ? NTOT1 : DH;
    const int idx = blockIdx.x * 256 + threadIdx.x;      // float4 index
    const int row  = idx / (NTOT / 4);
    const int colg = (idx % (NTOT / 4)) * 4;             // global col (mult of 4)

    float4 s = *(const float4*)&g_part[0][(size_t)idx * 4];
    float4 p1 = *(const float4*)&g_part[1][(size_t)idx * 4];
    float4 p2 = *(const float4*)&g_part[2][(size_t)idx * 4];
    float4 p3 = *(const float4*)&g_part[3][(size_t)idx * 4];
    s.x += p1.x; s.y += p1.y; s.z += p1.z; s.w += p1.w;
    s.x += p2.x; s.y += p2.y; s.z += p2.z; s.w += p2.w;
    s.x += p3.x; s.y += p3.y; s.z += p3.z; s.w += p3.w;

    if (MODE == 0) {
        const float4 b = *(const float4*)&bias0[colg];
        float4 o;
        const float v0 = s.x + b.x, v1 = s.y + b.y, v2 = s.z + b.z, v3 = s.w + b.w;
        o.x = v0 > 0.f ? v0 : expm1f(v0);
        o.y = v1 > 0.f ? v1 : expm1f(v1);
        o.z = v2 > 0.f ? v2 : expm1f(v2);
        o.w = v3 > 0.f ? v3 : expm1f(v3);
        *(float4*)&g_rep[row * DH + colg] = o;
    } else if (MODE == 1) {
        const int region = colg >> 9;          // 0,1,2 (512-col regions)
        const int colw = colg & (DH - 1);
        if (region == 0) {
            const float4 b0 = *(const float4*)&bias0[colw];
            const float4 bl = *(const float4*)&blog[colw];
            float4 o;
            o.x = (s.x + b0.x + bl.x) * KCNST;
            o.y = (s.y + b0.y + bl.y) * KCNST;
            o.z = (s.z + b0.z + bl.z) * KCNST;
            o.w = (s.w + b0.w + bl.w) * KCNST;
            *(float4*)&g_dep2[row * DH + colw] = o;
        } else if (region == 1) {
            const float4 b1 = *(const float4*)&bias1[colw];
            float4 o;
            o.x = (s.x + b1.x) * KCNST;
            o.y = (s.y + b1.y) * KCNST;
            o.z = (s.z + b1.z) * KCNST;
            o.w = (s.w + b1.w) * KCNST;
            *(float4*)&g_head2[row * DH + colw] = o;
        } else {
            *(float4*)&g_gate1[row * DH + colw] = s;
        }
    } else {
        const int i = row * DH + colg;
        const float4 b  = *(const float4*)&bias0[colg];   // bf
        const float4 g1 = *(const float4*)&g_gate1[i];
        const float4 rp = *(const float4*)&g_rep[i];
        const float4 at = *(const float4*)&g_attn[i];
        float4 o;
        {
            const float z = g1.x + s.x + b.x;
            const float gg = 1.f / (1.f + expf(-z));
            o.x = fmaf(gg, rp.x - at.x, at.x);
        }
        {
            const float z = g1.y + s.y + b.y;
            const float gg = 1.f / (1.f + expf(-z));
            o.y = fmaf(gg, rp.y - at.y, at.y);
        }
        {
            const float z = g1.z + s.z + b.z;
            const float gg = 1.f / (1.f + expf(-z));
            o.z = fmaf(gg, rp.z - at.z, at.z);
        }
        {
            const float z = g1.w + s.w + b.w;
            const float gg = 1.f / (1.f + expf(-z));
            o.w = fmaf(gg, rp.w - at.w, at.w);
        }
        *(float4*)&dout[i] = o;
    }
}

// =====================================================================
// Fused masked tanh-logit softmax + weighted sum over dependents.
// CTA = (batch, pair p). p<127: rows {p, 254-p} (work p+1 and 255-p sum
// to a constant 256, and the j-ranges nest so loads are shared).
// p=127: row 127 alone.
// p=128: row 255. Fully masked row: in fp32 the reference's logits+(-1e9)
//   round to exactly -1e9 for every j, so the reference softmax is exactly
//   UNIFORM 1/256 -> attn = mean_j rep[j].
// =====================================================================
__device__ __forceinline__ float wfun(float x) {
    const float t = ex2f(x);              // exp(-2u)
    const float r = rcpf(1.f + t);
    return ex2f(fmaf(TWOC2, r, -C2CNST)); // exp(C*tanh(u))
}

__global__ void __launch_bounds__(512) attn_kernel()
{
    const int cta = blockIdx.x;
    const int b = cta / 129;
    const int p = cta - b * 129;
    const int h = threadIdx.x;

    const float* __restrict__ dep = g_dep2  + b * LSEQ * DH;
    const float* __restrict__ hd  = g_head2 + b * LSEQ * DH;
    const float* __restrict__ rp  = g_rep   + b * LSEQ * DH;

    if (p == 128) {
        float s = 0.f;
        #pragma unroll 8
        for (int j = 0; j < LSEQ; ++j)
            s += rp[j * DH + h];
        g_attn[(b * LSEQ + 255) * DH + h] = s * (1.0f / 256.0f);
        return;
    }

    int i1, i2, jstart, jmid;
    if (p < 127)       { i1 = p;   i2 = 254 - p; jstart = p + 1; jmid = 255 - p; }
    else               { i1 = 127; i2 = -1;      jstart = 128;   jmid = 256; }

    const float h1 = hd[i1 * DH + h];
    const float h2 = (i2 >= 0) ? hd[i2 * DH + h] : 0.f;

    float n1 = 0.f, d1 = 0.f, n2 = 0.f, d2 = 0.f;
    int j = jstart;
    #pragma unroll 4
    for (; j < jmid; ++j) {
        const float dj = dep[j * DH + h];
        const float rj = rp [j * DH + h];
        const float w  = wfun(dj + h1);
        n1 = fmaf(w, rj, n1); d1 += w;
    }
    #pragma unroll 4
    for (; j < 256; ++j) {
        const float dj = dep[j * DH + h];
        const float rj = rp [j * DH + h];
        const float wa = wfun(dj + h1);
        n1 = fmaf(wa, rj, n1); d1 += wa;
        const float wb = wfun(dj + h2);
        n2 = fmaf(wb, rj, n2); d2 += wb;
    }
    g_attn[(b * LSEQ + i1) * DH + h] = n1 / d1;
    if (i2 >= 0)
        g_attn[(b * LSEQ + i2) * DH + h] = n2 / d2;
}

// =====================================================================
extern "C" void kernel_launch(void* const* d_in, const int* in_sizes, int n_in,
                              void* d_out, int out_size)
{
    const float* x       = (const float*)d_in[0];
    const float* fc_w    = (const float*)d_in[1];
    const float* fc_b    = (const float*)d_in[2];
    const float* w1_w    = (const float*)d_in[3];
    const float* w1_b    = (const float*)d_in[4];
    const float* w2_w    = (const float*)d_in[5];
    const float* w2_b    = (const float*)d_in[6];
    const float* b_logit = (const float*)d_in[7];
    const float* wf1_w   = (const float*)d_in[8];
    const float* wf2_w   = (const float*)d_in[9];
    const float* bf      = (const float*)d_in[10];
    float* out = (float*)d_out;

    // 1) rep = elu(x @ fc_w + fc_b)
    gemm_split_kernel<0><<<dim3(8, 16, NSPLIT), 128>>>(x, fc_w, nullptr, nullptr);
    epi_kernel<0><<<256, 256>>>(fc_b, nullptr, nullptr, nullptr);
    // 2) dep2/head2/gate1 = rep @ {w1,w2,wf1} (+biases, pre-scaled for exp2)
    gemm_split_kernel<1><<<dim3(8, 48, NSPLIT), 128>>>(nullptr, w1_w, w2_w, wf1_w);
    epi_kernel<1><<<768, 256>>>(w1_b, w2_b, b_logit, nullptr);
    // 3) fused masked softmax attention over dependents
    attn_kernel<<<2 * 129, 512>>>();
    // 4) out = sigmoid(gate1 + attn@wf2 + bf) * rep + (1-g) * attn
    gemm_split_kernel<2><<<dim3(8, 16, NSPLIT), 128>>>(nullptr, wf2_w, nullptr, nullptr);
    epi_kernel<2><<<256, 256>>>(bf, nullptr, nullptr, out);
}

// round 7
// speedup vs baseline: 1.3457x; 1.1976x over previous
#include <cuda_runtime.h>
#include <cuda_bf16.h>
#include <math.h>
#include <stdint.h>

// Problem constants: B=2, L=256, d_e=d_h=512
#define DH   512
#define LSEQ 256
#define MTOT 512   // B*L rows

// ---------------- scratch (no allocations allowed) ----------------
__device__ __align__(16) float g_rep  [MTOT*DH];
__device__ __align__(16) float g_dep2 [MTOT*DH];   // (dep + w1_b + b_logit) * KC
__device__ __align__(16) float g_head2[MTOT*DH];   // (head + w2_b) * KC
__device__ __align__(16) float g_gate1[MTOT*DH];   // rep @ wf1
__device__ __align__(16) float g_attn [MTOT*DH];

// bf16 split operands
__device__ __align__(16) __nv_bfloat16 g_Wthi[5 * DH * DH];  // W^T hi, [N,K] K-major
__device__ __align__(16) __nv_bfloat16 g_Wtlo[5 * DH * DH];
__device__ __align__(16) __nv_bfloat16 g_xhi[MTOT * DH];     // x split (gemm0 A)
__device__ __align__(16) __nv_bfloat16 g_xlo[MTOT * DH];
__device__ __align__(16) __nv_bfloat16 g_Ahi[MTOT * DH];     // rep split, then attn split
__device__ __align__(16) __nv_bfloat16 g_Alo[MTOT * DH];

// ---------------- math helpers ----------------
__device__ __forceinline__ float ex2f(float x) {
    float r; asm("ex2.approx.f32 %0, %1;" : "=f"(r) : "f"(x)); return r;
}
__device__ __forceinline__ float rcpf(float x) {
    float r; asm("rcp.approx.f32 %0, %1;" : "=f"(r) : "f"(x)); return r;
}
#define KCNST  (-0.57707801635558536f)   // -2*log2e/5
#define C2CNST (7.2134752044448170f)     // 5*log2e
#define TWOC2  (14.426950408889634f)

__device__ __forceinline__ void split_bf16(float v, __nv_bfloat16 &hi, __nv_bfloat16 &lo) {
    hi = __float2bfloat16(v);
    lo = __float2bfloat16(v - __bfloat162float(hi));
}

// ---------------- cp.async + mma.sync (sm_80 features, legal on sm_100) ----
__device__ __forceinline__ uint32_t smem_u32(const void* p) {
    uint32_t a;
    asm("{ .reg .u64 t; cvta.to.shared.u64 t, %1; cvt.u32.u64 %0, t; }" : "=r"(a) : "l"(p));
    return a;
}
__device__ __forceinline__ void cp_async16(uint32_t saddr, const void* g) {
    asm volatile("cp.async.cg.shared.global [%0], [%1], 16;" :: "r"(saddr), "l"(g) : "memory");
}
__device__ __forceinline__ void cp_commit() {
    asm volatile("cp.async.commit_group;" ::: "memory");
}
__device__ __forceinline__ void cp_wait0() {
    asm volatile("cp.async.wait_group 0;" ::: "memory");
}
// m16n8k16 row.col bf16 -> f32 accumulate
__device__ __forceinline__ void mma_bf16(float* d, const uint32_t* a, const uint32_t* b) {
    asm volatile(
        "mma.sync.aligned.m16n8k16.row.col.f32.bf16.bf16.f32 "
        "{%0,%1,%2,%3}, {%4,%5,%6,%7}, {%8,%9}, {%0,%1,%2,%3};"
        : "+f"(d[0]), "+f"(d[1]), "+f"(d[2]), "+f"(d[3])
        : "r"(a[0]), "r"(a[1]), "r"(a[2]), "r"(a[3]), "r"(b[0]), "r"(b[1]));
}

// =====================================================================
// Pre-pass: transpose + bf16-split the 5 weights.
// W [K=512, N=512] fp32 row-major -> Wt_hi/lo [N, K] bf16 K-major.
// =====================================================================
__global__ void __launch_bounds__(256) transpose_split_w(
    const float* __restrict__ w0, const float* __restrict__ w1,
    const float* __restrict__ w2, const float* __restrict__ w3,
    const float* __restrict__ w4)
{
    __shared__ float t[32][33];
    const int z = blockIdx.z;
    const float* W = (z == 0) ? w0 : (z == 1) ? w1 : (z == 2) ? w2 : (z == 3) ? w3 : w4;
    const int bi = blockIdx.x;   // k tile
    const int bj = blockIdx.y;   // n tile
    const int r  = threadIdx.x >> 3;
    const int c4 = (threadIdx.x & 7) * 4;

    const float4 v = *(const float4*)&W[(bi * 32 + r) * DH + bj * 32 + c4];
    t[r][c4 + 0] = v.x; t[r][c4 + 1] = v.y; t[r][c4 + 2] = v.z; t[r][c4 + 3] = v.w;
    __syncthreads();

    const size_t base = (size_t)z * DH * DH + (size_t)(bj * 32 + r) * DH + bi * 32 + c4;
    #pragma unroll
    for (int i = 0; i < 4; ++i) {
        const float a = t[c4 + i][r];
        __nv_bfloat16 hi, lo; split_bf16(a, hi, lo);
        g_Wthi[base + i] = hi;
        g_Wtlo[base + i] = lo;
    }
}

// Pre-pass: split x -> g_xhi/g_xlo.
__global__ void __launch_bounds__(256) split_x_kernel(const float* __restrict__ x)
{
    const int i = blockIdx.x * 256 + threadIdx.x;   // float4 index
    const float4 v = *(const float4*)&x[(size_t)i * 4];
    __nv_bfloat16 h0, l0, h1, l1, h2, l2, h3, l3;
    split_bf16(v.x, h0, l0); split_bf16(v.y, h1, l1);
    split_bf16(v.z, h2, l2); split_bf16(v.w, h3, l3);
    const size_t o = (size_t)i * 4;
    g_xhi[o] = h0; g_xhi[o+1] = h1; g_xhi[o+2] = h2; g_xhi[o+3] = h3;
    g_xlo[o] = l0; g_xlo[o+1] = l1; g_xlo[o+2] = l2; g_xlo[o+3] = l3;
}

// =====================================================================
// mma.sync GEMM: CTA tile 64x64, 4 warps (warp tile 32x32 = 2x4 atoms),
// K=512 in 8 chunks of 64, double-buffered cp.async.
// Split-bf16 3-pass: hi*hi + hi*lo + lo*hi, fp32 accumulators.
// MODE 0: A=x split,    B=Wt[0](fc),   epi: elu -> g_rep + split
// MODE 1: A=rep split,  B=Wt[1..3],    epi -> g_dep2/g_head2/g_gate1
// MODE 2: A=attn split, B=Wt[4](wf2),  epi: gate fusion -> dout
// =====================================================================
#define SROW 72            // smem row stride in bf16 (padding for banks)
#define ARRB (64 * SROW * 2)       // 9216 bytes per array
#define BUFB (4 * ARRB)            // 36864 bytes per buffer
#define SMTOT (2 * BUFB)           // 73728

template<int MODE>
__global__ void __launch_bounds__(128) gemm_mma(
    const float* __restrict__ b0v, const float* __restrict__ b1v,
    const float* __restrict__ b2v, float* __restrict__ dout)
{
    extern __shared__ char sm[];
    const uint32_t sbase = smem_u32(sm);
    const int tid  = threadIdx.x;
    const int warp = tid >> 5, lane = tid & 31;
    const int grp  = lane >> 2, tig = lane & 3;
    const int wm   = (warp >> 1) * 32;        // warp M offset in CTA tile
    const int wn   = (warp & 1) * 32;         // warp N offset

    const int m0 = blockIdx.x * 64;
    int n0, widx, region = 0;
    if (MODE == 1) { region = blockIdx.y >> 3; n0 = (blockIdx.y & 7) * 64; widx = 1 + region; }
    else           { n0 = blockIdx.y * 64; widx = (MODE == 0) ? 0 : 4; }

    const __nv_bfloat16* __restrict__ Ah = (MODE == 0) ? g_xhi : g_Ahi;
    const __nv_bfloat16* __restrict__ Al = (MODE == 0) ? g_xlo : g_Alo;
    const __nv_bfloat16* __restrict__ Bh = g_Wthi + (size_t)widx * DH * DH;
    const __nv_bfloat16* __restrict__ Bl = g_Wtlo + (size_t)widx * DH * DH;

    // ---- async loader: chunk c (64 k) into buffer buf. 2048 x 16B total. ----
    auto issue = [&](int c, int buf) {
        #pragma unroll
        for (int i = 0; i < 16; ++i) {
            const int idx = tid + i * 128;
            const int arr = idx >> 9;           // 0:Ah 1:Al 2:Bh 3:Bl
            const int row = (idx >> 3) & 63;
            const int kv  = (idx & 7) * 8;
            const __nv_bfloat16* gp =
                (arr == 0 ? Ah : arr == 1 ? Al : arr == 2 ? Bh : Bl)
                + (size_t)((arr < 2 ? m0 : n0) + row) * DH + c * 64 + kv;
            const uint32_t sa = sbase + buf * BUFB + arr * ARRB + (row * SROW + kv) * 2;
            cp_async16(sa, gp);
        }
        cp_commit();
    };

    float acc[2][4][4] = {};   // [matom][natom][reg]

    auto compute = [&](int buf) {
        const char* base = sm + buf * BUFB;
        const char* A0 = base;
        const char* A1 = base + ARRB;
        const char* B0 = base + 2 * ARRB;
        const char* B1 = base + 3 * ARRB;
        #pragma unroll
        for (int ks = 0; ks < 4; ++ks) {
            const int kb = ks * 16 + 2 * tig;
            uint32_t ah[2][4], al[2][4], bh[4][2], bl[4][2];
            #pragma unroll
            for (int ma = 0; ma < 2; ++ma) {
                const int r = wm + ma * 16 + grp;
                ah[ma][0] = *(const uint32_t*)(A0 + (r * SROW + kb) * 2);
                ah[ma][1] = *(const uint32_t*)(A0 + ((r + 8) * SROW + kb) * 2);
                ah[ma][2] = *(const uint32_t*)(A0 + (r * SROW + kb + 8) * 2);
                ah[ma][3] = *(const uint32_t*)(A0 + ((r + 8) * SROW + kb + 8) * 2);
                al[ma][0] = *(const uint32_t*)(A1 + (r * SROW + kb) * 2);
                al[ma][1] = *(const uint32_t*)(A1 + ((r + 8) * SROW + kb) * 2);
                al[ma][2] = *(const uint32_t*)(A1 + (r * SROW + kb + 8) * 2);
                al[ma][3] = *(const uint32_t*)(A1 + ((r + 8) * SROW + kb + 8) * 2);
            }
            #pragma unroll
            for (int nb = 0; nb < 4; ++nb) {
                const int r = wn + nb * 8 + grp;
                bh[nb][0] = *(const uint32_t*)(B0 + (r * SROW + kb) * 2);
                bh[nb][1] = *(const uint32_t*)(B0 + (r * SROW + kb + 8) * 2);
                bl[nb][0] = *(const uint32_t*)(B1 + (r * SROW + kb) * 2);
                bl[nb][1] = *(const uint32_t*)(B1 + (r * SROW + kb + 8) * 2);
            }
            #pragma unroll
            for (int ma = 0; ma < 2; ++ma)
                #pragma unroll
                for (int nb = 0; nb < 4; ++nb) {
                    mma_bf16(acc[ma][nb], ah[ma], bh[nb]);
                    mma_bf16(acc[ma][nb], ah[ma], bl[nb]);
                    mma_bf16(acc[ma][nb], al[ma], bh[nb]);
                }
        }
    };

    // ---- pipelined K loop ----
    issue(0, 0);
    cp_wait0();
    __syncthreads();
    #pragma unroll 1
    for (int c = 0; c < 8; ++c) {
        if (c < 7) issue(c + 1, (c + 1) & 1);
        compute(c & 1);
        if (c < 7) { cp_wait0(); __syncthreads(); }
    }

    // ---- fused epilogue: each thread owns 8 (row, col-pair) cells ----
    #pragma unroll
    for (int ma = 0; ma < 2; ++ma) {
        #pragma unroll
        for (int nb = 0; nb < 4; ++nb) {
            const float* d = acc[ma][nb];
            const int col = n0 + wn + nb * 8 + 2 * tig;
            #pragma unroll
            for (int half = 0; half < 2; ++half) {
                const int row = m0 + wm + ma * 16 + grp + half * 8;
                const float v0 = d[half * 2 + 0];
                const float v1 = d[half * 2 + 1];
                const size_t idx = (size_t)row * DH + col;
                if (MODE == 0) {
                    const float s0 = v0 + b0v[col], s1 = v1 + b0v[col + 1];
                    const float r0 = s0 > 0.f ? s0 : expm1f(s0);
                    const float r1 = s1 > 0.f ? s1 : expm1f(s1);
                    g_rep[idx] = r0; g_rep[idx + 1] = r1;
                    __nv_bfloat16 h, l;
                    split_bf16(r0, h, l); g_Ahi[idx]     = h; g_Alo[idx]     = l;
                    split_bf16(r1, h, l); g_Ahi[idx + 1] = h; g_Alo[idx + 1] = l;
                } else if (MODE == 1) {
                    if (region == 0) {
                        g_dep2[idx]     = (v0 + b0v[col]     + b2v[col])     * KCNST;
                        g_dep2[idx + 1] = (v1 + b0v[col + 1] + b2v[col + 1]) * KCNST;
                    } else if (region == 1) {
                        g_head2[idx]     = (v0 + b1v[col])     * KCNST;
                        g_head2[idx + 1] = (v1 + b1v[col + 1]) * KCNST;
                    } else {
                        g_gate1[idx] = v0; g_gate1[idx + 1] = v1;
                    }
                } else {
                    const float z0 = g_gate1[idx]     + v0 + b0v[col];
                    const float z1 = g_gate1[idx + 1] + v1 + b0v[col + 1];
                    const float gg0 = 1.f / (1.f + expf(-z0));
                    const float gg1 = 1.f / (1.f + expf(-z1));
                    const float a0 = g_attn[idx], a1 = g_attn[idx + 1];
                    dout[idx]     = fmaf(gg0, g_rep[idx]     - a0, a0);
                    dout[idx + 1] = fmaf(gg1, g_rep[idx + 1] - a1, a1);
                }
            }
        }
    }
}

// =====================================================================
// Fused masked tanh-logit softmax + weighted sum over dependents.
// grid (258, 2): blockIdx.x -> (batch, pair p), blockIdx.y -> channel half.
// p<127: rows {p, 254-p} (work sums to 256, j-ranges nest). p=127: row 127.
// p=128: row 255, FULLY masked: reference's logits+(-1e9) round to exactly
//   -1e9 in fp32 (ulp(1e9)=64 >> |C*tanh|<=5) -> softmax exactly uniform
//   -> attn = mean_j rep[j].
// Writes g_attn fp32 AND bf16 split into g_Ahi/g_Alo (gemm2 A operand).
// =====================================================================
__device__ __forceinline__ float wfun(float x) {
    const float t = ex2f(x);              // exp(-2u)
    const float r = rcpf(1.f + t);
    return ex2f(fmaf(TWOC2, r, -C2CNST)); // exp(C*tanh(u))
}
__device__ __forceinline__ void store_attn(int idx, float v) {
    g_attn[idx] = v;
    __nv_bfloat16 hi, lo; split_bf16(v, hi, lo);
    g_Ahi[idx] = hi; g_Alo[idx] = lo;
}

__global__ void __launch_bounds__(256) attn_kernel()
{
    const int cta = blockIdx.x;
    const int b = cta / 129;
    const int p = cta - b * 129;
    const int h = blockIdx.y * 256 + threadIdx.x;

    const float* __restrict__ dep = g_dep2  + b * LSEQ * DH;
    const float* __restrict__ hd  = g_head2 + b * LSEQ * DH;
    const float* __restrict__ rp  = g_rep   + b * LSEQ * DH;

    if (p == 128) {
        float s = 0.f;
        #pragma unroll 8
        for (int j = 0; j < LSEQ; ++j)
            s += rp[j * DH + h];
        store_attn((b * LSEQ + 255) * DH + h, s * (1.0f / 256.0f));
        return;
    }

    int i1, i2, jstart, jmid;
    if (p < 127)       { i1 = p;   i2 = 254 - p; jstart = p + 1; jmid = 255 - p; }
    else               { i1 = 127; i2 = -1;      jstart = 128;   jmid = 256; }

    const float h1 = hd[i1 * DH + h];
    const float h2 = (i2 >= 0) ? hd[i2 * DH + h] : 0.f;

    float n1 = 0.f, d1 = 0.f, n2 = 0.f, d2 = 0.f;
    int j = jstart;
    #pragma unroll 4
    for (; j < jmid; ++j) {
        const float dj = dep[j * DH + h];
        const float rj = rp [j * DH + h];
        const float w  = wfun(dj + h1);
        n1 = fmaf(w, rj, n1); d1 += w;
    }
    #pragma unroll 4
    for (; j < 256; ++j) {
        const float dj = dep[j * DH + h];
        const float rj = rp [j * DH + h];
        const float wa = wfun(dj + h1);
        n1 = fmaf(wa, rj, n1); d1 += wa;
        const float wb = wfun(dj + h2);
        n2 = fmaf(wb, rj, n2); d2 += wb;
    }
    store_attn((b * LSEQ + i1) * DH + h, n1 / d1);
    if (i2 >= 0)
        store_attn((b * LSEQ + i2) * DH + h, n2 / d2);
}

// =====================================================================
extern "C" void kernel_launch(void* const* d_in, const int* in_sizes, int n_in,
                              void* d_out, int out_size)
{
    const float* x       = (const float*)d_in[0];
    const float* fc_w    = (const float*)d_in[1];
    const float* fc_b    = (const float*)d_in[2];
    const float* w1_w    = (const float*)d_in[3];
    const float* w1_b    = (const float*)d_in[4];
    const float* w2_w    = (const float*)d_in[5];
    const float* w2_b    = (const float*)d_in[6];
    const float* b_logit = (const float*)d_in[7];
    const float* wf1_w   = (const float*)d_in[8];
    const float* wf2_w   = (const float*)d_in[9];
    const float* bf      = (const float*)d_in[10];
    float* out = (float*)d_out;

    static bool attr_done = false;
    if (!attr_done) {
        cudaFuncSetAttribute(gemm_mma<0>, cudaFuncAttributeMaxDynamicSharedMemorySize, SMTOT);
        cudaFuncSetAttribute(gemm_mma<1>, cudaFuncAttributeMaxDynamicSharedMemorySize, SMTOT);
        cudaFuncSetAttribute(gemm_mma<2>, cudaFuncAttributeMaxDynamicSharedMemorySize, SMTOT);
        attr_done = true;
    }

    // 0) weight transpose+split and x split
    transpose_split_w<<<dim3(16, 16, 5), 256>>>(fc_w, w1_w, w2_w, wf1_w, wf2_w);
    split_x_kernel<<<256, 256>>>(x);
    // 1) rep = elu(x @ fc_w + fc_b)   (+ bf16 split of rep)
    gemm_mma<0><<<dim3(8, 8), 128, SMTOT>>>(fc_b, nullptr, nullptr, nullptr);
    // 2) dep2/head2/gate1 = rep @ {w1,w2,wf1}
    gemm_mma<1><<<dim3(8, 24), 128, SMTOT>>>(w1_b, w2_b, b_logit, nullptr);
    // 3) fused masked softmax attention (+ bf16 split of attn)
    attn_kernel<<<dim3(258, 2), 256>>>();
    // 4) out = sigmoid(gate1 + attn@wf2 + bf) * rep + (1-g) * attn
    gemm_mma<2><<<dim3(8, 8), 128, SMTOT>>>(bf, nullptr, nullptr, out);
}